// round 1
// baseline (speedup 1.0000x reference)
#include <cuda_runtime.h>
#include <cuda_bf16.h>

// DilationLayerExtSE: out[b,c,h,w] = max_{di,dj in 5x5}( zeropad2(x)[b,c,h+di,w+dj] + w[b,c,di,dj] ) + bias[b,c]
// Shapes: x [8,128,128,128] f32, weight [8,128,5,5] f32, bias [8,128] f32. stride=1, pad=2.
//
// Design: one block per (b,c) plane (1024 blocks, 256 threads).
//   tid%32  -> column group (4 output cols, float4-aligned)
//   tid/32  -> row strip (16 output rows)
// Each thread keeps a 5-row x 12-col register window of x (rotated by full
// unroll, static indexing), slides down 16 rows loading 1 new row (3 LDG.128)
// per output row, computes 4 outputs (25 FADD + 24 FMNMX each, bias folded
// into the 25 weights), stores one STG.128 per row. Zero-padding handled by
// zeroing out-of-range chunks (reference zero-pads x BEFORE adding weight).

#define H_DIM 128
#define W_DIM 128

__global__ __launch_bounds__(256)
void dilation_kernel(const float* __restrict__ x,
                     const float* __restrict__ wgt,
                     const float* __restrict__ bias,
                     float* __restrict__ out) {
    const int plane = blockIdx.x;            // b*C + c, 0..1023
    const int tid   = threadIdx.x;
    const int cg    = tid & 31;              // column group 0..31
    const int strip = tid >> 5;              // 0..7
    const int colbase = cg << 2;             // output col base (multiple of 4)
    const int r0      = strip << 4;          // first output row of this strip

    const float* __restrict__ xp = x   + (size_t)plane * (H_DIM * W_DIM);
    float*       __restrict__ op = out + (size_t)plane * (H_DIM * W_DIM);
    const float* __restrict__ wp = wgt + plane * 25;
    const float b = __ldg(&bias[plane]);

    // weights with bias folded in (uniform across block -> L1 broadcast)
    float wb[25];
#pragma unroll
    for (int k = 0; k < 25; ++k) wb[k] = __ldg(&wp[k]) + b;

    // sliding window: 5 rows x 12 cols; col index 0 == global col (colbase-4)
    float buf[5][12];
    const float4 z4 = make_float4(0.f, 0.f, 0.f, 0.f);

#define LOADROW(rowexpr, slot) do {                                         \
    const int rr_ = (rowexpr);                                              \
    float4 A_ = z4, B_ = z4, C_ = z4;                                       \
    if (rr_ >= 0 && rr_ < H_DIM) {                                          \
        const float4* rp_ = reinterpret_cast<const float4*>(xp + rr_ * W_DIM); \
        if (cg >= 1)  A_ = __ldg(&rp_[cg - 1]);                             \
        B_ = __ldg(&rp_[cg]);                                               \
        if (cg <= 30) C_ = __ldg(&rp_[cg + 1]);                             \
    }                                                                       \
    buf[slot][0]  = A_.x; buf[slot][1]  = A_.y;                             \
    buf[slot][2]  = A_.z; buf[slot][3]  = A_.w;                             \
    buf[slot][4]  = B_.x; buf[slot][5]  = B_.y;                             \
    buf[slot][6]  = B_.z; buf[slot][7]  = B_.w;                             \
    buf[slot][8]  = C_.x; buf[slot][9]  = C_.y;                             \
    buf[slot][10] = C_.z; buf[slot][11] = C_.w;                             \
} while (0)

    // Prime window with input rows r0-2 .. r0+1 (slots 0..3).
    LOADROW(r0 - 2, 0);
    LOADROW(r0 - 1, 1);
    LOADROW(r0 + 0, 2);
    LOADROW(r0 + 1, 3);

    // Full unroll keeps buf indices static -> pure register file, no spills.
#pragma unroll
    for (int hh = 0; hh < 16; ++hh) {
        LOADROW(r0 + hh + 2, (hh + 4) % 5);

        // Input row for kernel tap di lives in slot (hh + di) % 5.
        // Output col (colbase+wo) tap (di,dj) reads buf[.][wo + dj + 2].
        float v0, v1, v2, v3;
        {
            const float* row = buf[hh % 5];   // di = 0
            v0 = row[2] + wb[0];
            v1 = row[3] + wb[0];
            v2 = row[4] + wb[0];
            v3 = row[5] + wb[0];
#pragma unroll
            for (int dj = 1; dj < 5; ++dj) {
                const float wv = wb[dj];
                v0 = fmaxf(v0, row[2 + dj] + wv);
                v1 = fmaxf(v1, row[3 + dj] + wv);
                v2 = fmaxf(v2, row[4 + dj] + wv);
                v3 = fmaxf(v3, row[5 + dj] + wv);
            }
        }
#pragma unroll
        for (int di = 1; di < 5; ++di) {
            const float* row = buf[(hh + di) % 5];
#pragma unroll
            for (int dj = 0; dj < 5; ++dj) {
                const float wv = wb[di * 5 + dj];
                v0 = fmaxf(v0, row[2 + dj] + wv);
                v1 = fmaxf(v1, row[3 + dj] + wv);
                v2 = fmaxf(v2, row[4 + dj] + wv);
                v3 = fmaxf(v3, row[5 + dj] + wv);
            }
        }

        *reinterpret_cast<float4*>(op + (size_t)(r0 + hh) * W_DIM + colbase) =
            make_float4(v0, v1, v2, v3);
    }
#undef LOADROW
}

extern "C" void kernel_launch(void* const* d_in, const int* in_sizes, int n_in,
                              void* d_out, int out_size) {
    (void)in_sizes; (void)n_in; (void)out_size;
    const float* x    = (const float*)d_in[0];   // [8,128,128,128]
    const float* wgt  = (const float*)d_in[1];   // [8,128,5,5]
    const float* bias = (const float*)d_in[2];   // [8,128]
    float* out = (float*)d_out;                  // [8,128,128,128]

    dilation_kernel<<<8 * 128, 256>>>(x, wgt, bias, out);
}